// round 7
// baseline (speedup 1.0000x reference)
#include <cuda_runtime.h>
#include <cuda_bf16.h>
#include <math.h>

#define TT 256
#define BB_ 256
#define DD 512
#define AA 32
#define LL 3
#define MM (TT*BB_)            // 65536 rows
#define TBD ((size_t)MM*DD)    // 33554432
#define BD (BB_*DD)            // 131072

// ---------------- scratch (device globals; no runtime allocation) -----------
__device__ float g_bufA[TT*BB_*DD];
__device__ float g_bufB[TT*BB_*DD];
__device__ float g_X[3ull*TT*BB_*DD];
__device__ float g_y[TT*BB_*DD];

// ---------------- SGEMM 128x128x8, fp32, optional bias ----------------------
// C[M,N] = A[M,K] @ W[K,N] (+ bias[N]); M%128==0, N%128==0, K%8==0
__global__ __launch_bounds__(256) void sgemm128(
    const float* __restrict__ A, const float* __restrict__ W,
    float* __restrict__ C, const float* __restrict__ bias,
    int M, int N, int K)
{
    __shared__ float As[8][128];
    __shared__ float Bs[8][128];
    const int bx = blockIdx.x;           // n tile
    const int by = blockIdx.y;           // m tile
    const int tid = threadIdx.x;
    const int tx = tid % 16, ty = tid / 16;

    const float* Ab = A + (size_t)by * 128 * K;
    const float* Wb = W + (size_t)bx * 128;

    const int arow = tid >> 1;           // 0..127
    const int acol = (tid & 1) * 4;      // 0 or 4
    const int brow = tid >> 5;           // 0..7
    const int bcol = (tid & 31) * 4;     // 0..124

    float acc[8][8];
    #pragma unroll
    for (int i = 0; i < 8; i++)
        #pragma unroll
        for (int j = 0; j < 8; j++) acc[i][j] = 0.f;

    for (int k0 = 0; k0 < K; k0 += 8) {
        float4 av = *(const float4*)(Ab + (size_t)arow * K + k0 + acol);
        As[acol + 0][arow] = av.x;
        As[acol + 1][arow] = av.y;
        As[acol + 2][arow] = av.z;
        As[acol + 3][arow] = av.w;
        float4 bv = *(const float4*)(Wb + (size_t)(k0 + brow) * N + bcol);
        *(float4*)(&Bs[brow][bcol]) = bv;
        __syncthreads();
        #pragma unroll
        for (int k = 0; k < 8; k++) {
            float4 a0 = *(const float4*)(&As[k][ty * 8]);
            float4 a1 = *(const float4*)(&As[k][ty * 8 + 4]);
            float4 b0 = *(const float4*)(&Bs[k][tx * 8]);
            float4 b1 = *(const float4*)(&Bs[k][tx * 8 + 4]);
            float af[8] = {a0.x,a0.y,a0.z,a0.w,a1.x,a1.y,a1.z,a1.w};
            float bf[8] = {b0.x,b0.y,b0.z,b0.w,b1.x,b1.y,b1.z,b1.w};
            #pragma unroll
            for (int i = 0; i < 8; i++)
                #pragma unroll
                for (int j = 0; j < 8; j++)
                    acc[i][j] += af[i] * bf[j];
        }
        __syncthreads();
    }

    #pragma unroll
    for (int i = 0; i < 8; i++) {
        size_t m = (size_t)by * 128 + ty * 8 + i;
        #pragma unroll
        for (int j = 0; j < 8; j += 4) {
            int n = bx * 128 + tx * 8 + j;
            float4 v = make_float4(acc[i][j], acc[i][j+1], acc[i][j+2], acc[i][j+3]);
            if (bias) {
                v.x += bias[n]; v.y += bias[n+1]; v.z += bias[n+2]; v.w += bias[n+3];
            }
            *(float4*)(C + m * N + n) = v;
        }
    }
}

// ---------------- row LayerNorm(+bias) + scale/shift + ReLU, in place --------
// X[row,512]; adds bias before stats (LN(x@W + b))
__global__ __launch_bounds__(128) void ln_bias_relu(
    float* __restrict__ X, const float* __restrict__ bias,
    const float* __restrict__ gamma, const float* __restrict__ beta)
{
    const int row = blockIdx.x;
    const int tid = threadIdx.x;        // 128 threads * float4 = 512
    float* xp = X + (size_t)row * DD + tid * 4;
    float4 v = *(float4*)xp;
    float4 bb = *(const float4*)(bias + tid * 4);
    v.x += bb.x; v.y += bb.y; v.z += bb.z; v.w += bb.w;

    float s  = v.x + v.y + v.z + v.w;
    float sq = v.x*v.x + v.y*v.y + v.z*v.z + v.w*v.w;
    #pragma unroll
    for (int o = 16; o > 0; o >>= 1) {
        s  += __shfl_down_sync(0xffffffffu, s,  o);
        sq += __shfl_down_sync(0xffffffffu, sq, o);
    }
    __shared__ float ws[4], wq[4];
    if ((tid & 31) == 0) { ws[tid >> 5] = s; wq[tid >> 5] = sq; }
    __syncthreads();
    float st = ws[0] + ws[1] + ws[2] + ws[3];
    float qt = wq[0] + wq[1] + wq[2] + wq[3];
    float mean = st * (1.f / DD);
    float var  = qt * (1.f / DD) - mean * mean;
    float inv  = rsqrtf(var + 1e-6f);

    float4 g = *(const float4*)(gamma + tid * 4);
    float4 b2 = *(const float4*)(beta + tid * 4);
    float4 o;
    o.x = fmaxf((v.x - mean) * inv * g.x + b2.x, 0.f);
    o.y = fmaxf((v.y - mean) * inv * g.y + b2.y, 0.f);
    o.z = fmaxf((v.z - mean) * inv * g.z + b2.z, 0.f);
    o.w = fmaxf((v.w - mean) * inv * g.w + b2.w, 0.f);
    *(float4*)xp = o;
}

// ---------------- fused GRU step --------------------------------------------
// h_new = (1-z)*n + z*h_eff, all 3 gate GEMMs fused.
// Block: 32 b-rows x 16 d-cols, 128 threads (dx=tid%16, by=tid/16, 4 rows each)
__device__ __forceinline__ float sigmoidf_(float x) { return 1.f / (1.f + expf(-x)); }

__global__ __launch_bounds__(128) void gru_step(
    const float* __restrict__ h_in,      // [B,512]  (y[t-1] or initial hidden)
    const float* __restrict__ Xr, const float* __restrict__ Xz,
    const float* __restrict__ Xn,        // [B,512] slices at step t (bias folded)
    const int* __restrict__ done,        // [B] (bool promoted to int32)
    const float* __restrict__ Wh,        // [3,512,512]
    const float* __restrict__ bhn,       // [512]
    float* __restrict__ h_out)           // y[t]  [B,512]
{
    constexpr int BBt = 32, DC = 16, BK = 32;
    __shared__ float hs[BBt][BK + 4];          // padded (stride 36)
    __shared__ float Wst[3][DC][BK + 4];       // transposed, padded

    const int d0 = blockIdx.x * DC;
    const int b0 = blockIdx.y * BBt;
    const int tid = threadIdx.x;
    const int dx = tid & 15;
    const int byq = tid >> 4;            // 0..7, handles 4 rows each

    // h-tile loader mapping
    const int lr = tid >> 2;             // 0..31
    const int lc = (tid & 3) * 8;        // 0,8,16,24
    const int gb = b0 + lr;
    const bool dn = done[gb] != 0;

    float accR[4] = {0,0,0,0}, accZ[4] = {0,0,0,0}, accN[4] = {0,0,0,0};

    for (int k0 = 0; k0 < DD; k0 += BK) {
        // load h tile (with done-reset masking)
        float4 v0, v1;
        if (dn) { v0 = make_float4(0,0,0,0); v1 = v0; }
        else {
            v0 = *(const float4*)(h_in + (size_t)gb * DD + k0 + lc);
            v1 = *(const float4*)(h_in + (size_t)gb * DD + k0 + lc + 4);
        }
        hs[lr][lc+0]=v0.x; hs[lr][lc+1]=v0.y; hs[lr][lc+2]=v0.z; hs[lr][lc+3]=v0.w;
        hs[lr][lc+4]=v1.x; hs[lr][lc+5]=v1.y; hs[lr][lc+6]=v1.z; hs[lr][lc+7]=v1.w;

        // load W tiles transposed: 3 gates * 32k * 16d = 384 float4, 3 per thread
        #pragma unroll
        for (int p = 0; p < 3; p++) {
            int q = tid + p * 128;               // 0..383
            int g = q >> 7;                      // 0..2
            int rem = q & 127;
            int kk = rem >> 2;                   // 0..31
            int dd4 = (rem & 3) * 4;             // 0,4,8,12
            float4 w = *(const float4*)(Wh + (size_t)g * DD * DD + (size_t)(k0 + kk) * DD + d0 + dd4);
            Wst[g][dd4+0][kk] = w.x;
            Wst[g][dd4+1][kk] = w.y;
            Wst[g][dd4+2][kk] = w.z;
            Wst[g][dd4+3][kk] = w.w;
        }
        __syncthreads();

        #pragma unroll
        for (int kk = 0; kk < BK; kk += 4) {
            float4 wr = *(const float4*)(&Wst[0][dx][kk]);
            float4 wz = *(const float4*)(&Wst[1][dx][kk]);
            float4 wn = *(const float4*)(&Wst[2][dx][kk]);
            #pragma unroll
            for (int i = 0; i < 4; i++) {
                float4 hv = *(const float4*)(&hs[byq * 4 + i][kk]);
                accR[i] += hv.x*wr.x + hv.y*wr.y + hv.z*wr.z + hv.w*wr.w;
                accZ[i] += hv.x*wz.x + hv.y*wz.y + hv.z*wz.z + hv.w*wz.w;
                accN[i] += hv.x*wn.x + hv.y*wn.y + hv.z*wn.z + hv.w*wn.w;
            }
        }
        __syncthreads();
    }

    const int d = d0 + dx;
    const float bh = bhn[d];
    #pragma unroll
    for (int i = 0; i < 4; i++) {
        int b = b0 + byq * 4 + i;
        size_t gi = (size_t)b * DD + d;
        float r = sigmoidf_(Xr[gi] + accR[i]);
        float z = sigmoidf_(Xz[gi] + accZ[i]);
        float n = tanhf(Xn[gi] + r * (accN[i] + bh));
        float hp = (done[b] != 0) ? 0.f : h_in[gi];
        h_out[gi] = (1.f - z) * n + z * hp;
    }
}

// ---------------- actor head: logits = X@Wa + ba, availability mask ----------
__global__ __launch_bounds__(256) void head_gemm(
    const float* __restrict__ X, const float* __restrict__ Wa,
    const float* __restrict__ ba, const int* __restrict__ avail,
    float* __restrict__ out, int M)
{
    const int r = blockIdx.x * 8 + (threadIdx.x >> 5);
    const int a = threadIdx.x & 31;
    const float* xr = X + (size_t)r * DD;
    float acc = 0.f;
    #pragma unroll 8
    for (int k = 0; k < DD; k += 4) {
        float4 xv = *(const float4*)(xr + k);
        acc += xv.x * __ldg(Wa + (k + 0) * AA + a);
        acc += xv.y * __ldg(Wa + (k + 1) * AA + a);
        acc += xv.z * __ldg(Wa + (k + 2) * AA + a);
        acc += xv.w * __ldg(Wa + (k + 3) * AA + a);
    }
    float av = (float)avail[(size_t)r * AA + a];
    out[(size_t)r * AA + a] = acc + ba[a] - (1.f - av) * 1e10f;
}

__global__ void copy_kernel(const float* __restrict__ src, float* __restrict__ dst, int n)
{
    int i = blockIdx.x * blockDim.x + threadIdx.x;
    if (i < n) dst[i] = src[i];
}

// ---------------- host orchestration ----------------------------------------
extern "C" void kernel_launch(void* const* d_in, const int* in_sizes, int n_in,
                              void* d_out, int out_size)
{
    const float*          hidden = (const float*)d_in[0];
    const float*          obs    = (const float*)d_in[1];
    const int*            dones  = (const int*)d_in[2];   // bool promoted to int32
    const int*            avail  = (const int*)d_in[3];
    const float*          Wm     = (const float*)d_in[4];
    const float*          bm     = (const float*)d_in[5];
    const float*          lns    = (const float*)d_in[6];
    const float*          lnb    = (const float*)d_in[7];
    const float*          Wi     = (const float*)d_in[8];
    const float*          bi     = (const float*)d_in[9];
    const float*          Wh     = (const float*)d_in[10];
    const float*          bhn    = (const float*)d_in[11];
    const float*          Wo     = (const float*)d_in[12];
    const float*          bo     = (const float*)d_in[13];
    const float*          ln2s   = (const float*)d_in[14];
    const float*          ln2b   = (const float*)d_in[15];
    const float*          Wa     = (const float*)d_in[16];
    const float*          ba     = (const float*)d_in[17];
    float* out = (float*)d_out;

    float *bufA, *bufB, *Xbuf, *ybuf;
    cudaGetSymbolAddress((void**)&bufA, g_bufA);
    cudaGetSymbolAddress((void**)&bufB, g_bufB);
    cudaGetSymbolAddress((void**)&Xbuf, g_X);
    cudaGetSymbolAddress((void**)&ybuf, g_y);

    const dim3 ggrid(DD / 128, MM / 128);   // (4, 512)
    float* bufs[2] = {bufA, bufB};

    // --- MLP encoder: 3x (GEMM -> LN(+bias) -> ReLU), ping-pong buffers ---
    const float* cur = obs;
    for (int l = 0; l < LL; l++) {
        float* dst = bufs[l & 1];
        sgemm128<<<ggrid, 256>>>(cur, Wm + (size_t)l * DD * DD, dst, nullptr, MM, DD, DD);
        ln_bias_relu<<<MM, 128>>>(dst, bm + l * DD, lns + l * DD, lnb + l * DD);
        cur = dst;
    }
    // cur == bufA after 3 layers

    // --- precompute input-gate activations for all t: X[g] = e @ Wi[g] + bi[g]
    for (int g = 0; g < 3; g++) {
        sgemm128<<<ggrid, 256>>>(cur, Wi + (size_t)g * DD * DD,
                                 Xbuf + (size_t)g * TBD, bi + g * DD, MM, DD, DD);
    }

    // --- sequential GRU scan: y[t] = h after step t ---
    const dim3 sgrid(DD / 16, BB_ / 32);    // (32, 8)
    for (int t = 0; t < TT; t++) {
        const float* h_in = (t == 0) ? hidden : (ybuf + (size_t)(t - 1) * BD);
        gru_step<<<sgrid, 128>>>(h_in,
                                 Xbuf + (size_t)t * BD,
                                 Xbuf + TBD + (size_t)t * BD,
                                 Xbuf + 2 * TBD + (size_t)t * BD,
                                 dones + (size_t)t * BB_,
                                 Wh, bhn,
                                 ybuf + (size_t)t * BD);
    }

    // --- actor head ---
    sgemm128<<<ggrid, 256>>>(ybuf, Wo, bufB, nullptr, MM, DD, DD);
    ln_bias_relu<<<MM, 128>>>(bufB, bo, ln2s, ln2b);

    bool has_hidden = (out_size >= (int)(BD + (size_t)MM * AA));
    float* logits_out = out + (has_hidden ? BD : 0);
    head_gemm<<<MM / 8, 256>>>(bufB, Wa, ba, avail, logits_out, MM);

    if (has_hidden) {
        copy_kernel<<<(BD + 255) / 256, 256>>>(ybuf + (size_t)(TT - 1) * BD, out, BD);
    }
}

// round 8
// speedup vs baseline: 1.2583x; 1.2583x over previous
#include <cuda_runtime.h>
#include <cuda_bf16.h>
#include <math.h>
#include <stdint.h>

#define TT 256
#define BB_ 256
#define DD 512
#define AA 32
#define LL 3
#define MM (TT*BB_)            // 65536 rows
#define TBD ((size_t)MM*DD)    // 33554432
#define BD (BB_*DD)            // 131072

// ---------------- scratch (device globals; no runtime allocation) -----------
__device__ float g_bufA[TT*BB_*DD];
__device__ float g_bufB[TT*BB_*DD];
__device__ float g_X[3ull*TT*BB_*DD];
__device__ float g_y[TT*BB_*DD];

// ---------------- tf32 helpers ----------------------------------------------
__device__ __forceinline__ uint32_t f2tf32(float x) {
    uint32_t r;
    asm("cvt.rna.tf32.f32 %0, %1;" : "=r"(r) : "f"(x));
    return r;
}

// ---------------- TF32 tensor-core GEMM 128x128x32 ---------------------------
// C[M,N] = A[M,K] @ W[K,N] (+ bias[N]); M%128==0, N%128==0, K%32==0
// 256 threads = 8 warps in 2(m) x 4(n); warp tile 64x32; mma.m16n8k8.tf32
__global__ __launch_bounds__(256) void gemm_tf32(
    const float* __restrict__ A, const float* __restrict__ W,
    float* __restrict__ C, const float* __restrict__ bias,
    int M, int N, int K)
{
    // As[m][k]: stride 36 -> bank (4m+k) conflict-free for frag loads
    // Bs[k][n]: stride 136 -> bank (8k+n) conflict-free for frag loads
    __shared__ uint32_t As[128][36];
    __shared__ uint32_t Bs[32][136];

    const int bx = blockIdx.x;          // n tile
    const int by = blockIdx.y;          // m tile
    const int tid = threadIdx.x;
    const int warp = tid >> 5, lane = tid & 31;
    const int wm = warp & 1, wn = warp >> 1;      // 2 x 4 warp grid
    const int m_w = wm * 64, n_w = wn * 32;
    const int g  = lane >> 2;           // groupID 0..7
    const int tg = lane & 3;            // threadInGroup 0..3

    float c[4][4][4];
    #pragma unroll
    for (int i = 0; i < 4; i++)
        #pragma unroll
        for (int j = 0; j < 4; j++)
            #pragma unroll
            for (int q = 0; q < 4; q++) c[i][j][q] = 0.f;

    const float* Ab = A + (size_t)by * 128 * K;
    const float* Wb = W + (size_t)bx * 128;

    for (int k0 = 0; k0 < K; k0 += 32) {
        // load A tile 128x32: 1024 float4, 4 per thread
        #pragma unroll
        for (int i = 0; i < 4; i++) {
            int idx = tid + i * 256;
            int row = idx >> 3;
            int kq  = (idx & 7) * 4;
            float4 v = *(const float4*)(Ab + (size_t)row * K + k0 + kq);
            uint4 u = make_uint4(f2tf32(v.x), f2tf32(v.y), f2tf32(v.z), f2tf32(v.w));
            *(uint4*)(&As[row][kq]) = u;
        }
        // load B tile 32x128: 1024 float4, 4 per thread
        #pragma unroll
        for (int i = 0; i < 4; i++) {
            int idx = tid + i * 256;
            int krow = idx >> 5;
            int nq   = (idx & 31) * 4;
            float4 v = *(const float4*)(Wb + (size_t)(k0 + krow) * N + nq);
            uint4 u = make_uint4(f2tf32(v.x), f2tf32(v.y), f2tf32(v.z), f2tf32(v.w));
            *(uint4*)(&Bs[krow][nq]) = u;
        }
        __syncthreads();

        #pragma unroll
        for (int kk = 0; kk < 4; kk++) {
            const int kb = kk * 8;
            // A fragments for 4 m-subtiles
            uint32_t af[4][4];
            #pragma unroll
            for (int mi = 0; mi < 4; mi++) {
                int rb = m_w + mi * 16;
                af[mi][0] = As[rb + g    ][kb + tg    ];
                af[mi][1] = As[rb + g + 8][kb + tg    ];
                af[mi][2] = As[rb + g    ][kb + tg + 4];
                af[mi][3] = As[rb + g + 8][kb + tg + 4];
            }
            // B fragments for 4 n-subtiles
            uint32_t bf[4][2];
            #pragma unroll
            for (int ni = 0; ni < 4; ni++) {
                int nb = n_w + ni * 8;
                bf[ni][0] = Bs[kb + tg    ][nb + g];
                bf[ni][1] = Bs[kb + tg + 4][nb + g];
            }
            #pragma unroll
            for (int mi = 0; mi < 4; mi++)
                #pragma unroll
                for (int ni = 0; ni < 4; ni++) {
                    asm volatile(
                        "mma.sync.aligned.m16n8k8.row.col.f32.tf32.tf32.f32 "
                        "{%0,%1,%2,%3}, {%4,%5,%6,%7}, {%8,%9}, {%0,%1,%2,%3};"
                        : "+f"(c[mi][ni][0]), "+f"(c[mi][ni][1]),
                          "+f"(c[mi][ni][2]), "+f"(c[mi][ni][3])
                        : "r"(af[mi][0]), "r"(af[mi][1]), "r"(af[mi][2]), "r"(af[mi][3]),
                          "r"(bf[ni][0]), "r"(bf[ni][1]));
                }
        }
        __syncthreads();
    }

    // epilogue: c0,c1 -> (row g, cols 2tg, 2tg+1); c2,c3 -> (row g+8, same cols)
    #pragma unroll
    for (int mi = 0; mi < 4; mi++) {
        int r0 = by * 128 + m_w + mi * 16 + g;
        #pragma unroll
        for (int ni = 0; ni < 4; ni++) {
            int cc = bx * 128 + n_w + ni * 8 + tg * 2;
            float b0 = 0.f, b1 = 0.f;
            if (bias) { b0 = bias[cc]; b1 = bias[cc + 1]; }
            float2 v0 = make_float2(c[mi][ni][0] + b0, c[mi][ni][1] + b1);
            float2 v1 = make_float2(c[mi][ni][2] + b0, c[mi][ni][3] + b1);
            *(float2*)(C + (size_t)r0 * N + cc)       = v0;
            *(float2*)(C + (size_t)(r0 + 8) * N + cc) = v1;
        }
    }
}

// ---------------- row LayerNorm(+bias) + scale/shift + ReLU, in place --------
__global__ __launch_bounds__(128) void ln_bias_relu(
    float* __restrict__ X, const float* __restrict__ bias,
    const float* __restrict__ gamma, const float* __restrict__ beta)
{
    const int row = blockIdx.x;
    const int tid = threadIdx.x;        // 128 threads * float4 = 512
    float* xp = X + (size_t)row * DD + tid * 4;
    float4 v = *(float4*)xp;
    float4 bb = *(const float4*)(bias + tid * 4);
    v.x += bb.x; v.y += bb.y; v.z += bb.z; v.w += bb.w;

    float s  = v.x + v.y + v.z + v.w;
    float sq = v.x*v.x + v.y*v.y + v.z*v.z + v.w*v.w;
    #pragma unroll
    for (int o = 16; o > 0; o >>= 1) {
        s  += __shfl_down_sync(0xffffffffu, s,  o);
        sq += __shfl_down_sync(0xffffffffu, sq, o);
    }
    __shared__ float ws[4], wq[4];
    if ((tid & 31) == 0) { ws[tid >> 5] = s; wq[tid >> 5] = sq; }
    __syncthreads();
    float st = ws[0] + ws[1] + ws[2] + ws[3];
    float qt = wq[0] + wq[1] + wq[2] + wq[3];
    float mean = st * (1.f / DD);
    float var  = qt * (1.f / DD) - mean * mean;
    float inv  = rsqrtf(var + 1e-6f);

    float4 g = *(const float4*)(gamma + tid * 4);
    float4 b2 = *(const float4*)(beta + tid * 4);
    float4 o;
    o.x = fmaxf((v.x - mean) * inv * g.x + b2.x, 0.f);
    o.y = fmaxf((v.y - mean) * inv * g.y + b2.y, 0.f);
    o.z = fmaxf((v.z - mean) * inv * g.z + b2.z, 0.f);
    o.w = fmaxf((v.w - mean) * inv * g.w + b2.w, 0.f);
    *(float4*)xp = o;
}

// ---------------- fused GRU step --------------------------------------------
__device__ __forceinline__ float sigmoidf_(float x) { return 1.f / (1.f + expf(-x)); }

__global__ __launch_bounds__(128) void gru_step(
    const float* __restrict__ h_in,
    const float* __restrict__ Xr, const float* __restrict__ Xz,
    const float* __restrict__ Xn,
    const int* __restrict__ done,        // bool promoted to int32
    const float* __restrict__ Wh,
    const float* __restrict__ bhn,
    float* __restrict__ h_out)
{
    constexpr int BBt = 32, DC = 16, BK = 32;
    __shared__ float hs[BBt][BK + 4];
    __shared__ float Wst[3][DC][BK + 4];

    const int d0 = blockIdx.x * DC;
    const int b0 = blockIdx.y * BBt;
    const int tid = threadIdx.x;
    const int dx = tid & 15;
    const int byq = tid >> 4;

    const int lr = tid >> 2;
    const int lc = (tid & 3) * 8;
    const int gb = b0 + lr;
    const bool dn = done[gb] != 0;

    float accR[4] = {0,0,0,0}, accZ[4] = {0,0,0,0}, accN[4] = {0,0,0,0};

    for (int k0 = 0; k0 < DD; k0 += BK) {
        float4 v0, v1;
        if (dn) { v0 = make_float4(0,0,0,0); v1 = v0; }
        else {
            v0 = *(const float4*)(h_in + (size_t)gb * DD + k0 + lc);
            v1 = *(const float4*)(h_in + (size_t)gb * DD + k0 + lc + 4);
        }
        hs[lr][lc+0]=v0.x; hs[lr][lc+1]=v0.y; hs[lr][lc+2]=v0.z; hs[lr][lc+3]=v0.w;
        hs[lr][lc+4]=v1.x; hs[lr][lc+5]=v1.y; hs[lr][lc+6]=v1.z; hs[lr][lc+7]=v1.w;

        #pragma unroll
        for (int p = 0; p < 3; p++) {
            int q = tid + p * 128;
            int gg = q >> 7;
            int rem = q & 127;
            int kk = rem >> 2;
            int dd4 = (rem & 3) * 4;
            float4 w = *(const float4*)(Wh + (size_t)gg * DD * DD + (size_t)(k0 + kk) * DD + d0 + dd4);
            Wst[gg][dd4+0][kk] = w.x;
            Wst[gg][dd4+1][kk] = w.y;
            Wst[gg][dd4+2][kk] = w.z;
            Wst[gg][dd4+3][kk] = w.w;
        }
        __syncthreads();

        #pragma unroll
        for (int kk = 0; kk < BK; kk += 4) {
            float4 wr = *(const float4*)(&Wst[0][dx][kk]);
            float4 wz = *(const float4*)(&Wst[1][dx][kk]);
            float4 wn = *(const float4*)(&Wst[2][dx][kk]);
            #pragma unroll
            for (int i = 0; i < 4; i++) {
                float4 hv = *(const float4*)(&hs[byq * 4 + i][kk]);
                accR[i] += hv.x*wr.x + hv.y*wr.y + hv.z*wr.z + hv.w*wr.w;
                accZ[i] += hv.x*wz.x + hv.y*wz.y + hv.z*wz.z + hv.w*wz.w;
                accN[i] += hv.x*wn.x + hv.y*wn.y + hv.z*wn.z + hv.w*wn.w;
            }
        }
        __syncthreads();
    }

    const int d = d0 + dx;
    const float bh = bhn[d];
    #pragma unroll
    for (int i = 0; i < 4; i++) {
        int b = b0 + byq * 4 + i;
        size_t gi = (size_t)b * DD + d;
        float r = sigmoidf_(Xr[gi] + accR[i]);
        float z = sigmoidf_(Xz[gi] + accZ[i]);
        float n = tanhf(Xn[gi] + r * (accN[i] + bh));
        float hp = (done[b] != 0) ? 0.f : h_in[gi];
        h_out[gi] = (1.f - z) * n + z * hp;
    }
}

// ---------------- actor head: logits = X@Wa + ba, availability mask ----------
__global__ __launch_bounds__(256) void head_gemm(
    const float* __restrict__ X, const float* __restrict__ Wa,
    const float* __restrict__ ba, const int* __restrict__ avail,
    float* __restrict__ out, int M)
{
    const int r = blockIdx.x * 8 + (threadIdx.x >> 5);
    const int a = threadIdx.x & 31;
    const float* xr = X + (size_t)r * DD;
    float acc = 0.f;
    #pragma unroll 8
    for (int k = 0; k < DD; k += 4) {
        float4 xv = *(const float4*)(xr + k);
        acc += xv.x * __ldg(Wa + (k + 0) * AA + a);
        acc += xv.y * __ldg(Wa + (k + 1) * AA + a);
        acc += xv.z * __ldg(Wa + (k + 2) * AA + a);
        acc += xv.w * __ldg(Wa + (k + 3) * AA + a);
    }
    float av = (float)avail[(size_t)r * AA + a];
    out[(size_t)r * AA + a] = acc + ba[a] - (1.f - av) * 1e10f;
}

__global__ void copy_kernel(const float* __restrict__ src, float* __restrict__ dst, int n)
{
    int i = blockIdx.x * blockDim.x + threadIdx.x;
    if (i < n) dst[i] = src[i];
}

// ---------------- host orchestration ----------------------------------------
extern "C" void kernel_launch(void* const* d_in, const int* in_sizes, int n_in,
                              void* d_out, int out_size)
{
    const float*          hidden = (const float*)d_in[0];
    const float*          obs    = (const float*)d_in[1];
    const int*            dones  = (const int*)d_in[2];   // bool promoted to int32
    const int*            avail  = (const int*)d_in[3];
    const float*          Wm     = (const float*)d_in[4];
    const float*          bm     = (const float*)d_in[5];
    const float*          lns    = (const float*)d_in[6];
    const float*          lnb    = (const float*)d_in[7];
    const float*          Wi     = (const float*)d_in[8];
    const float*          bi     = (const float*)d_in[9];
    const float*          Wh     = (const float*)d_in[10];
    const float*          bhn    = (const float*)d_in[11];
    const float*          Wo     = (const float*)d_in[12];
    const float*          bo     = (const float*)d_in[13];
    const float*          ln2s   = (const float*)d_in[14];
    const float*          ln2b   = (const float*)d_in[15];
    const float*          Wa     = (const float*)d_in[16];
    const float*          ba     = (const float*)d_in[17];
    float* out = (float*)d_out;

    float *bufA, *bufB, *Xbuf, *ybuf;
    cudaGetSymbolAddress((void**)&bufA, g_bufA);
    cudaGetSymbolAddress((void**)&bufB, g_bufB);
    cudaGetSymbolAddress((void**)&Xbuf, g_X);
    cudaGetSymbolAddress((void**)&ybuf, g_y);

    const dim3 ggrid(DD / 128, MM / 128);   // (4, 512)
    float* bufs[2] = {bufA, bufB};

    // --- MLP encoder: 3x (GEMM -> LN(+bias) -> ReLU), ping-pong buffers ---
    const float* cur = obs;
    for (int l = 0; l < LL; l++) {
        float* dst = bufs[l & 1];
        gemm_tf32<<<ggrid, 256>>>(cur, Wm + (size_t)l * DD * DD, dst, nullptr, MM, DD, DD);
        ln_bias_relu<<<MM, 128>>>(dst, bm + l * DD, lns + l * DD, lnb + l * DD);
        cur = dst;
    }
    // cur == bufA after 3 layers

    // --- precompute input-gate activations for all t: X[g] = e @ Wi[g] + bi[g]
    for (int g = 0; g < 3; g++) {
        gemm_tf32<<<ggrid, 256>>>(cur, Wi + (size_t)g * DD * DD,
                                  Xbuf + (size_t)g * TBD, bi + g * DD, MM, DD, DD);
    }

    // --- sequential GRU scan: y[t] = h after step t ---
    const dim3 sgrid(DD / 16, BB_ / 32);    // (32, 8)
    for (int t = 0; t < TT; t++) {
        const float* h_in = (t == 0) ? hidden : (ybuf + (size_t)(t - 1) * BD);
        gru_step<<<sgrid, 128>>>(h_in,
                                 Xbuf + (size_t)t * BD,
                                 Xbuf + TBD + (size_t)t * BD,
                                 Xbuf + 2 * TBD + (size_t)t * BD,
                                 dones + (size_t)t * BB_,
                                 Wh, bhn,
                                 ybuf + (size_t)t * BD);
    }

    // --- actor head ---
    gemm_tf32<<<ggrid, 256>>>(ybuf, Wo, bufB, nullptr, MM, DD, DD);
    ln_bias_relu<<<MM, 128>>>(bufB, bo, ln2s, ln2b);

    bool has_hidden = (out_size >= (int)(BD + (size_t)MM * AA));
    float* logits_out = out + (has_hidden ? BD : 0);
    head_gemm<<<MM / 8, 256>>>(bufB, Wa, ba, avail, logits_out, MM);

    if (has_hidden) {
        copy_kernel<<<(BD + 255) / 256, 256>>>(ybuf + (size_t)(TT - 1) * BD, out, BD);
    }
}

// round 9
// speedup vs baseline: 1.6726x; 1.3292x over previous
#include <cuda_runtime.h>
#include <cuda_bf16.h>
#include <math.h>
#include <stdint.h>

#define TT 256
#define BB_ 256
#define DD 512
#define AA 32
#define LL 3
#define MM (TT*BB_)            // 65536 rows
#define TBD ((size_t)MM*DD)    // 33554432
#define BD (BB_*DD)            // 131072

// ---------------- scratch (device globals; no runtime allocation) -----------
__device__ float g_bufA[TT*BB_*DD];
__device__ float g_bufB[TT*BB_*DD];
__device__ float g_X[3ull*TT*BB_*DD];
__device__ float g_y[TT*BB_*DD];

// grid-barrier state for persistent GRU scan
__device__ unsigned g_bar_count = 0;
__device__ unsigned g_bar_gen   = 0;

// ---------------- tf32 helpers ----------------------------------------------
__device__ __forceinline__ uint32_t f2tf32(float x) {
    uint32_t r;
    asm("cvt.rna.tf32.f32 %0, %1;" : "=r"(r) : "f"(x));
    return r;
}

__device__ __forceinline__ unsigned ld_acquire_u32(unsigned* p) {
    unsigned v;
    asm volatile("ld.acquire.gpu.u32 %0, [%1];" : "=r"(v) : "l"(p) : "memory");
    return v;
}

// release/acquire grid barrier; all NBLK blocks must be co-resident
__device__ __forceinline__ void grid_barrier(unsigned nblk) {
    __threadfence();
    __syncthreads();
    if (threadIdx.x == 0) {
        unsigned gen = *((volatile unsigned*)&g_bar_gen);   // read BEFORE arrive
        unsigned arrived = atomicAdd(&g_bar_count, 1u);
        if (arrived == nblk - 1) {
            g_bar_count = 0;
            __threadfence();
            atomicAdd(&g_bar_gen, 1u);
        } else {
            while (ld_acquire_u32(&g_bar_gen) == gen) { __nanosleep(64); }
        }
    }
    __syncthreads();
}

// ---------------- TF32 tensor-core GEMM 128x128x32 ---------------------------
// C[M,N] = A[M,K] @ W[K,N] (+ bias[N]); M%128==0, N%128==0, K%32==0
__global__ __launch_bounds__(256) void gemm_tf32(
    const float* __restrict__ A, const float* __restrict__ W,
    float* __restrict__ C, const float* __restrict__ bias,
    int M, int N, int K)
{
    __shared__ uint32_t As[128][36];
    __shared__ uint32_t Bs[32][136];

    const int bx = blockIdx.x;
    const int by = blockIdx.y;
    const int tid = threadIdx.x;
    const int warp = tid >> 5, lane = tid & 31;
    const int wm = warp & 1, wn = warp >> 1;
    const int m_w = wm * 64, n_w = wn * 32;
    const int g  = lane >> 2;
    const int tg = lane & 3;

    float c[4][4][4];
    #pragma unroll
    for (int i = 0; i < 4; i++)
        #pragma unroll
        for (int j = 0; j < 4; j++)
            #pragma unroll
            for (int q = 0; q < 4; q++) c[i][j][q] = 0.f;

    const float* Ab = A + (size_t)by * 128 * K;
    const float* Wb = W + (size_t)bx * 128;

    for (int k0 = 0; k0 < K; k0 += 32) {
        #pragma unroll
        for (int i = 0; i < 4; i++) {
            int idx = tid + i * 256;
            int row = idx >> 3;
            int kq  = (idx & 7) * 4;
            float4 v = *(const float4*)(Ab + (size_t)row * K + k0 + kq);
            uint4 u = make_uint4(f2tf32(v.x), f2tf32(v.y), f2tf32(v.z), f2tf32(v.w));
            *(uint4*)(&As[row][kq]) = u;
        }
        #pragma unroll
        for (int i = 0; i < 4; i++) {
            int idx = tid + i * 256;
            int krow = idx >> 5;
            int nq   = (idx & 31) * 4;
            float4 v = *(const float4*)(Wb + (size_t)(k0 + krow) * N + nq);
            uint4 u = make_uint4(f2tf32(v.x), f2tf32(v.y), f2tf32(v.z), f2tf32(v.w));
            *(uint4*)(&Bs[krow][nq]) = u;
        }
        __syncthreads();

        #pragma unroll
        for (int kk = 0; kk < 4; kk++) {
            const int kb = kk * 8;
            uint32_t af[4][4];
            #pragma unroll
            for (int mi = 0; mi < 4; mi++) {
                int rb = m_w + mi * 16;
                af[mi][0] = As[rb + g    ][kb + tg    ];
                af[mi][1] = As[rb + g + 8][kb + tg    ];
                af[mi][2] = As[rb + g    ][kb + tg + 4];
                af[mi][3] = As[rb + g + 8][kb + tg + 4];
            }
            uint32_t bf[4][2];
            #pragma unroll
            for (int ni = 0; ni < 4; ni++) {
                int nb = n_w + ni * 8;
                bf[ni][0] = Bs[kb + tg    ][nb + g];
                bf[ni][1] = Bs[kb + tg + 4][nb + g];
            }
            #pragma unroll
            for (int mi = 0; mi < 4; mi++)
                #pragma unroll
                for (int ni = 0; ni < 4; ni++) {
                    asm volatile(
                        "mma.sync.aligned.m16n8k8.row.col.f32.tf32.tf32.f32 "
                        "{%0,%1,%2,%3}, {%4,%5,%6,%7}, {%8,%9}, {%0,%1,%2,%3};"
                        : "+f"(c[mi][ni][0]), "+f"(c[mi][ni][1]),
                          "+f"(c[mi][ni][2]), "+f"(c[mi][ni][3])
                        : "r"(af[mi][0]), "r"(af[mi][1]), "r"(af[mi][2]), "r"(af[mi][3]),
                          "r"(bf[ni][0]), "r"(bf[ni][1]));
                }
        }
        __syncthreads();
    }

    #pragma unroll
    for (int mi = 0; mi < 4; mi++) {
        int r0 = by * 128 + m_w + mi * 16 + g;
        #pragma unroll
        for (int ni = 0; ni < 4; ni++) {
            int cc = bx * 128 + n_w + ni * 8 + tg * 2;
            float b0 = 0.f, b1 = 0.f;
            if (bias) { b0 = bias[cc]; b1 = bias[cc + 1]; }
            float2 v0 = make_float2(c[mi][ni][0] + b0, c[mi][ni][1] + b1);
            float2 v1 = make_float2(c[mi][ni][2] + b0, c[mi][ni][3] + b1);
            *(float2*)(C + (size_t)r0 * N + cc)       = v0;
            *(float2*)(C + (size_t)(r0 + 8) * N + cc) = v1;
        }
    }
}

// ---------------- row LayerNorm(+bias) + scale/shift + ReLU, in place --------
__global__ __launch_bounds__(128) void ln_bias_relu(
    float* __restrict__ X, const float* __restrict__ bias,
    const float* __restrict__ gamma, const float* __restrict__ beta)
{
    const int row = blockIdx.x;
    const int tid = threadIdx.x;
    float* xp = X + (size_t)row * DD + tid * 4;
    float4 v = *(float4*)xp;
    float4 bb = *(const float4*)(bias + tid * 4);
    v.x += bb.x; v.y += bb.y; v.z += bb.z; v.w += bb.w;

    float s  = v.x + v.y + v.z + v.w;
    float sq = v.x*v.x + v.y*v.y + v.z*v.z + v.w*v.w;
    #pragma unroll
    for (int o = 16; o > 0; o >>= 1) {
        s  += __shfl_down_sync(0xffffffffu, s,  o);
        sq += __shfl_down_sync(0xffffffffu, sq, o);
    }
    __shared__ float ws[4], wq[4];
    if ((tid & 31) == 0) { ws[tid >> 5] = s; wq[tid >> 5] = sq; }
    __syncthreads();
    float st = ws[0] + ws[1] + ws[2] + ws[3];
    float qt = wq[0] + wq[1] + wq[2] + wq[3];
    float mean = st * (1.f / DD);
    float var  = qt * (1.f / DD) - mean * mean;
    float inv  = rsqrtf(var + 1e-6f);

    float4 g = *(const float4*)(gamma + tid * 4);
    float4 b2 = *(const float4*)(beta + tid * 4);
    float4 o;
    o.x = fmaxf((v.x - mean) * inv * g.x + b2.x, 0.f);
    o.y = fmaxf((v.y - mean) * inv * g.y + b2.y, 0.f);
    o.z = fmaxf((v.z - mean) * inv * g.z + b2.z, 0.f);
    o.w = fmaxf((v.w - mean) * inv * g.w + b2.w, 0.f);
    *(float4*)xp = o;
}

// ---------------- persistent GRU scan (tf32 mma + grid barrier) --------------
// 64 blocks x 256 threads. Block bi: batch half nb=bi>>5 (128 rows),
// d-slice nd=bi&31 (16 cols per gate). Warp grid 4(m=32) x 2(n=8).
// Weights Wh[3][512][d0..d0+16) staged once in smem as tf32.
// Per step: stage h (tf32, done-masked) in 4 k-chunks of 128, mma all 3 gates,
// elementwise update in registers, write y[t], grid barrier.
#define GRU_NBLK 64
#define GRU_SMEM_WORDS (3*512*16 + 128*132)    // Ws + hs = 41472 words

__device__ __forceinline__ float sigmoidf_(float x) { return 1.f / (1.f + expf(-x)); }

__global__ __launch_bounds__(256, 1) void gru_scan(
    const float* __restrict__ hidden,    // [256,512] initial h
    const float* __restrict__ X,         // [3][T][B][D] gate inputs (bias folded)
    const int* __restrict__ dones,       // [T][B] bool->int32
    const float* __restrict__ Wh,        // [3,512,512]
    const float* __restrict__ bhn,       // [512]
    float* __restrict__ y)               // [T][B][D]
{
    extern __shared__ uint32_t smem_u[];
    uint32_t* Ws = smem_u;               // [gate][k][16]  (3*512*16)
    uint32_t* hs = smem_u + 3*512*16;    // [128][132]

    const int bi = blockIdx.x;
    const int nb = bi >> 5;              // batch half
    const int nd = bi & 31;              // d-slice
    const int b0 = nb * 128;
    const int d0 = nd * 16;

    const int tid  = threadIdx.x;
    const int warp = tid >> 5, lane = tid & 31;
    const int wm = warp & 3, wn = warp >> 2;       // 4(m) x 2(n)
    const int m_base = wm * 32;
    const int n8 = wn * 8;
    const int g  = lane >> 2;
    const int tg = lane & 3;

    // ---- stage weights once: Wh[gate][k][d0..d0+16) -> Ws tf32 ----
    #pragma unroll 4
    for (int i = 0; i < 24; i++) {
        int q = tid + i * 256;           // 0..6143 float4-quads
        int gate = q >> 11;
        int rem  = q & 2047;
        int k    = rem >> 2;
        int dl4  = (rem & 3) * 4;
        float4 w = *(const float4*)(Wh + ((size_t)gate * 512 + k) * 512 + d0 + dl4);
        uint4 u = make_uint4(f2tf32(w.x), f2tf32(w.y), f2tf32(w.z), f2tf32(w.w));
        *(uint4*)(&Ws[((gate << 9) + k) * 16 + dl4]) = u;
    }

    const int dcol = d0 + n8 + tg * 2;   // this lane's two output columns
    const float bh0 = bhn[dcol], bh1 = bhn[dcol + 1];
    __syncthreads();

    for (int t = 0; t < TT; t++) {
        const float* hprev = (t == 0) ? hidden : (y + (size_t)(t - 1) * BD);
        const int* dn = dones + (size_t)t * BB_;

        // ---- prefetch epilogue operands (j = mi*2 + half; row = m_base + j*8 + g) ----
        float2 xr2[4], xz2[4], xn2[4], hp2[4];
        #pragma unroll
        for (int j = 0; j < 4; j++) {
            int bglob = b0 + m_base + j * 8 + g;
            int df = dn[bglob];
            size_t gi = (size_t)bglob * DD + dcol;
            hp2[j] = df ? make_float2(0.f, 0.f) : *(const float2*)(hprev + gi);
            size_t xi = (size_t)t * BD + gi;
            xr2[j] = *(const float2*)(X + xi);
            xz2[j] = *(const float2*)(X + TBD + xi);
            xn2[j] = *(const float2*)(X + 2 * TBD + xi);
        }

        float c[2][3][4];
        #pragma unroll
        for (int mi = 0; mi < 2; mi++)
            #pragma unroll
            for (int gt = 0; gt < 3; gt++)
                #pragma unroll
                for (int q = 0; q < 4; q++) c[mi][gt][q] = 0.f;

        // ---- 4 k-chunks of 128 ----
        for (int kc = 0; kc < 4; kc++) {
            const int kbase = kc * 128;
            // stage h chunk (tf32, done-masked)
            #pragma unroll 4
            for (int i = 0; i < 16; i++) {
                int linear = tid + i * 256;
                int row = linear >> 5;            // 0..127
                int c4  = (linear & 31) * 4;      // 0..124
                int gb  = b0 + row;
                float4 v;
                if (dn[gb]) v = make_float4(0.f, 0.f, 0.f, 0.f);
                else v = *(const float4*)(hprev + (size_t)gb * DD + kbase + c4);
                uint4 u = make_uint4(f2tf32(v.x), f2tf32(v.y), f2tf32(v.z), f2tf32(v.w));
                *(uint4*)(&hs[row * 132 + c4]) = u;
            }
            __syncthreads();

            #pragma unroll 4
            for (int kt = 0; kt < 16; kt++) {
                const int kb = kt * 8;
                uint32_t af[2][4];
                #pragma unroll
                for (int mi = 0; mi < 2; mi++) {
                    int rb = (m_base + mi * 16 + g) * 132;
                    af[mi][0] = hs[rb +       kb + tg    ];
                    af[mi][1] = hs[rb + 8*132 + kb + tg  ];
                    af[mi][2] = hs[rb +       kb + tg + 4];
                    af[mi][3] = hs[rb + 8*132 + kb + tg + 4];
                }
                #pragma unroll
                for (int gt = 0; gt < 3; gt++) {
                    int kg = kbase + kb;
                    uint32_t b0r = Ws[((gt << 9) + kg + tg    ) * 16 + n8 + g];
                    uint32_t b1r = Ws[((gt << 9) + kg + tg + 4) * 16 + n8 + g];
                    #pragma unroll
                    for (int mi = 0; mi < 2; mi++) {
                        asm volatile(
                            "mma.sync.aligned.m16n8k8.row.col.f32.tf32.tf32.f32 "
                            "{%0,%1,%2,%3}, {%4,%5,%6,%7}, {%8,%9}, {%0,%1,%2,%3};"
                            : "+f"(c[mi][gt][0]), "+f"(c[mi][gt][1]),
                              "+f"(c[mi][gt][2]), "+f"(c[mi][gt][3])
                            : "r"(af[mi][0]), "r"(af[mi][1]), "r"(af[mi][2]), "r"(af[mi][3]),
                              "r"(b0r), "r"(b1r));
                    }
                }
            }
            __syncthreads();
        }

        // ---- elementwise GRU update, write y[t] ----
        #pragma unroll
        for (int mi = 0; mi < 2; mi++) {
            #pragma unroll
            for (int half = 0; half < 2; half++) {
                int j = mi * 2 + half;
                int q0 = half * 2;
                int bglob = b0 + m_base + j * 8 + g;
                float r0 = sigmoidf_(xr2[j].x + c[mi][0][q0]);
                float r1 = sigmoidf_(xr2[j].y + c[mi][0][q0 + 1]);
                float z0 = sigmoidf_(xz2[j].x + c[mi][1][q0]);
                float z1 = sigmoidf_(xz2[j].y + c[mi][1][q0 + 1]);
                float n0 = tanhf(xn2[j].x + r0 * (c[mi][2][q0]     + bh0));
                float n1 = tanhf(xn2[j].y + r1 * (c[mi][2][q0 + 1] + bh1));
                float2 o;
                o.x = (1.f - z0) * n0 + z0 * hp2[j].x;
                o.y = (1.f - z1) * n1 + z1 * hp2[j].y;
                *(float2*)(y + (size_t)t * BD + (size_t)bglob * DD + dcol) = o;
            }
        }

        grid_barrier(GRU_NBLK);
    }
}

// ---------------- actor head: logits = X@Wa + ba, availability mask ----------
__global__ __launch_bounds__(256) void head_gemm(
    const float* __restrict__ X, const float* __restrict__ Wa,
    const float* __restrict__ ba, const int* __restrict__ avail,
    float* __restrict__ out, int M)
{
    const int r = blockIdx.x * 8 + (threadIdx.x >> 5);
    const int a = threadIdx.x & 31;
    const float* xr = X + (size_t)r * DD;
    float acc = 0.f;
    #pragma unroll 8
    for (int k = 0; k < DD; k += 4) {
        float4 xv = *(const float4*)(xr + k);
        acc += xv.x * __ldg(Wa + (k + 0) * AA + a);
        acc += xv.y * __ldg(Wa + (k + 1) * AA + a);
        acc += xv.z * __ldg(Wa + (k + 2) * AA + a);
        acc += xv.w * __ldg(Wa + (k + 3) * AA + a);
    }
    float av = (float)avail[(size_t)r * AA + a];
    out[(size_t)r * AA + a] = acc + ba[a] - (1.f - av) * 1e10f;
}

__global__ void copy_kernel(const float* __restrict__ src, float* __restrict__ dst, int n)
{
    int i = blockIdx.x * blockDim.x + threadIdx.x;
    if (i < n) dst[i] = src[i];
}

// ---------------- host orchestration ----------------------------------------
extern "C" void kernel_launch(void* const* d_in, const int* in_sizes, int n_in,
                              void* d_out, int out_size)
{
    const float*          hidden = (const float*)d_in[0];
    const float*          obs    = (const float*)d_in[1];
    const int*            dones  = (const int*)d_in[2];   // bool promoted to int32
    const int*            avail  = (const int*)d_in[3];
    const float*          Wm     = (const float*)d_in[4];
    const float*          bm     = (const float*)d_in[5];
    const float*          lns    = (const float*)d_in[6];
    const float*          lnb    = (const float*)d_in[7];
    const float*          Wi     = (const float*)d_in[8];
    const float*          bi     = (const float*)d_in[9];
    const float*          Wh     = (const float*)d_in[10];
    const float*          bhn    = (const float*)d_in[11];
    const float*          Wo     = (const float*)d_in[12];
    const float*          bo     = (const float*)d_in[13];
    const float*          ln2s   = (const float*)d_in[14];
    const float*          ln2b   = (const float*)d_in[15];
    const float*          Wa     = (const float*)d_in[16];
    const float*          ba     = (const float*)d_in[17];
    float* out = (float*)d_out;

    float *bufA, *bufB, *Xbuf, *ybuf;
    cudaGetSymbolAddress((void**)&bufA, g_bufA);
    cudaGetSymbolAddress((void**)&bufB, g_bufB);
    cudaGetSymbolAddress((void**)&Xbuf, g_X);
    cudaGetSymbolAddress((void**)&ybuf, g_y);

    const dim3 ggrid(DD / 128, MM / 128);   // (4, 512)
    float* bufs[2] = {bufA, bufB};

    // --- MLP encoder: 3x (GEMM -> LN(+bias) -> ReLU), ping-pong buffers ---
    const float* cur = obs;
    for (int l = 0; l < LL; l++) {
        float* dst = bufs[l & 1];
        gemm_tf32<<<ggrid, 256>>>(cur, Wm + (size_t)l * DD * DD, dst, nullptr, MM, DD, DD);
        ln_bias_relu<<<MM, 128>>>(dst, bm + l * DD, lns + l * DD, lnb + l * DD);
        cur = dst;
    }

    // --- precompute input-gate activations for all t: X[g] = e @ Wi[g] + bi[g]
    for (int g = 0; g < 3; g++) {
        gemm_tf32<<<ggrid, 256>>>(cur, Wi + (size_t)g * DD * DD,
                                  Xbuf + (size_t)g * TBD, bi + g * DD, MM, DD, DD);
    }

    // --- persistent GRU scan: all 256 steps in one kernel ---
    static const int gru_smem = GRU_SMEM_WORDS * 4;   // 165888 bytes
    cudaFuncSetAttribute(gru_scan, cudaFuncAttributeMaxDynamicSharedMemorySize, gru_smem);
    gru_scan<<<GRU_NBLK, 256, gru_smem>>>(hidden, Xbuf, dones, Wh, bhn, ybuf);

    // --- actor head ---
    gemm_tf32<<<ggrid, 256>>>(ybuf, Wo, bufB, nullptr, MM, DD, DD);
    ln_bias_relu<<<MM, 128>>>(bufB, bo, ln2s, ln2b);

    bool has_hidden = (out_size >= (int)(BD + (size_t)MM * AA));
    float* logits_out = out + (has_hidden ? BD : 0);
    head_gemm<<<MM / 8, 256>>>(bufB, Wa, ba, avail, logits_out, MM);

    if (has_hidden) {
        copy_kernel<<<(BD + 255) / 256, 256>>>(ybuf + (size_t)(TT - 1) * BD, out, BD);
    }
}

// round 11
// speedup vs baseline: 1.8597x; 1.1119x over previous
#include <cuda_runtime.h>
#include <cuda_bf16.h>
#include <math.h>
#include <stdint.h>

#define TT 256
#define BB_ 256
#define DD 512
#define AA 32
#define LL 3
#define MM (TT*BB_)            // 65536 rows
#define TBD ((size_t)MM*DD)    // 33554432
#define BD (BB_*DD)            // 131072

// ---------------- scratch (device globals; no runtime allocation) -----------
__device__ float g_bufA[TT*BB_*DD];
__device__ float g_bufB[TT*BB_*DD];
__device__ float g_X[3ull*TT*BB_*DD];
__device__ float g_y[TT*BB_*DD];

// grid-barrier state for persistent GRU scan
__device__ unsigned g_bar_count = 0;
__device__ unsigned g_bar_gen   = 0;

// ---------------- helpers ----------------------------------------------------
__device__ __forceinline__ uint32_t f2tf32(float x) {
    uint32_t r;
    asm("cvt.rna.tf32.f32 %0, %1;" : "=r"(r) : "f"(x));
    return r;
}

__device__ __forceinline__ void cp_async16(void* smem_ptr, const void* gmem_ptr) {
    uint32_t s = (uint32_t)__cvta_generic_to_shared(smem_ptr);
    asm volatile("cp.async.cg.shared.global [%0], [%1], 16;" :: "r"(s), "l"(gmem_ptr));
}

__device__ __forceinline__ unsigned ld_acquire_u32(unsigned* p) {
    unsigned v;
    asm volatile("ld.acquire.gpu.u32 %0, [%1];" : "=r"(v) : "l"(p) : "memory");
    return v;
}

// release/acquire grid barrier; all NBLK blocks must be co-resident
__device__ __forceinline__ void grid_barrier(unsigned nblk) {
    __threadfence();
    __syncthreads();
    if (threadIdx.x == 0) {
        unsigned gen = *((volatile unsigned*)&g_bar_gen);   // read BEFORE arrive
        unsigned arrived = atomicAdd(&g_bar_count, 1u);
        if (arrived == nblk - 1) {
            g_bar_count = 0;
            __threadfence();
            atomicAdd(&g_bar_gen, 1u);
        } else {
            while (ld_acquire_u32(&g_bar_gen) == gen) { __nanosleep(64); }
        }
    }
    __syncthreads();
}

// ---------------- TF32 tensor-core GEMM 128x128x32, cp.async 2-stage ---------
// C[M,N] = A[M,K] @ W[K,N] (+ bias[N]); M%128==0, N%128==0, K%32==0
// dynamic smem: As[2][128][36] raw fp32, Bs[2][32][136] raw fp32 (70 KB)
#define GEMM_SMEM_BYTES ((2*128*36 + 2*32*136) * 4)

__global__ __launch_bounds__(256) void gemm_tf32(
    const float* __restrict__ A, const float* __restrict__ W,
    float* __restrict__ C, const float* __restrict__ bias,
    int M, int N, int K)
{
    extern __shared__ float sm[];
    float* AsBase = sm;                  // stage s at s*4608, [row*36 + k]
    float* BsBase = sm + 2 * 4608;       // stage s at s*4352, [krow*136 + n]

    const int bx = blockIdx.x;
    const int by = blockIdx.y;
    const int tid = threadIdx.x;
    const int warp = tid >> 5, lane = tid & 31;
    const int wm = warp & 1, wn = warp >> 1;
    const int m_w = wm * 64, n_w = wn * 32;
    const int g  = lane >> 2;
    const int tg = lane & 3;

    const float* Ab = A + (size_t)by * 128 * K;
    const float* Wb = W + (size_t)bx * 128;

    // per-thread load coords
    const int a_row = tid >> 1;                 // 0..127  (2 threads/row)
    const int a_kq  = (tid & 1) * 16;           // float index 0 or 16; FOUR 16B each
    const int b_kr  = tid >> 5;                 // 0..7
    const int b_nq  = (tid & 31) * 4;

    float c[4][4][4];
    #pragma unroll
    for (int i = 0; i < 4; i++)
        #pragma unroll
        for (int j = 0; j < 4; j++)
            #pragma unroll
            for (int q = 0; q < 4; q++) c[i][j][q] = 0.f;

    // async load of one 128x32 A tile + 32x128 B tile into stage s
    auto issue_load = [&](int k0, int s) {
        float* As = AsBase + s * 4608;
        float* Bs = BsBase + s * 4352;
        // A: 128 rows x 32 floats; each thread: 16 floats = 4 x 16B on its row
        #pragma unroll
        for (int i = 0; i < 4; i++) {
            cp_async16(&As[a_row * 36 + a_kq + i * 4],
                       Ab + (size_t)a_row * K + k0 + a_kq + i * 4);
        }
        // B: 32 rows x 128 floats; each thread: 4 rows, 16B each
        #pragma unroll
        for (int i = 0; i < 4; i++) {
            int kr = b_kr + i * 8;
            cp_async16(&Bs[kr * 136 + b_nq],
                       Wb + (size_t)(k0 + kr) * N + b_nq);
        }
        asm volatile("cp.async.commit_group;");
    };

    issue_load(0, 0);

    int s = 0;
    for (int k0 = 0; k0 < K; k0 += 32, s ^= 1) {
        if (k0 + 32 < K) {
            issue_load(k0 + 32, s ^ 1);
            asm volatile("cp.async.wait_group 1;");
        } else {
            asm volatile("cp.async.wait_group 0;");
        }
        __syncthreads();

        const float* As = AsBase + s * 4608;
        const float* Bs = BsBase + s * 4352;

        #pragma unroll
        for (int kk = 0; kk < 4; kk++) {
            const int kb = kk * 8;
            uint32_t af[4][4];
            #pragma unroll
            for (int mi = 0; mi < 4; mi++) {
                int rb = m_w + mi * 16;
                af[mi][0] = f2tf32(As[(rb + g    ) * 36 + kb + tg    ]);
                af[mi][1] = f2tf32(As[(rb + g + 8) * 36 + kb + tg    ]);
                af[mi][2] = f2tf32(As[(rb + g    ) * 36 + kb + tg + 4]);
                af[mi][3] = f2tf32(As[(rb + g + 8) * 36 + kb + tg + 4]);
            }
            uint32_t bf[4][2];
            #pragma unroll
            for (int ni = 0; ni < 4; ni++) {
                int nb = n_w + ni * 8;
                bf[ni][0] = f2tf32(Bs[(kb + tg    ) * 136 + nb + g]);
                bf[ni][1] = f2tf32(Bs[(kb + tg + 4) * 136 + nb + g]);
            }
            #pragma unroll
            for (int mi = 0; mi < 4; mi++)
                #pragma unroll
                for (int ni = 0; ni < 4; ni++) {
                    asm volatile(
                        "mma.sync.aligned.m16n8k8.row.col.f32.tf32.tf32.f32 "
                        "{%0,%1,%2,%3}, {%4,%5,%6,%7}, {%8,%9}, {%0,%1,%2,%3};"
                        : "+f"(c[mi][ni][0]), "+f"(c[mi][ni][1]),
                          "+f"(c[mi][ni][2]), "+f"(c[mi][ni][3])
                        : "r"(af[mi][0]), "r"(af[mi][1]), "r"(af[mi][2]), "r"(af[mi][3]),
                          "r"(bf[ni][0]), "r"(bf[ni][1]));
                }
        }
        __syncthreads();
    }

    #pragma unroll
    for (int mi = 0; mi < 4; mi++) {
        int r0 = by * 128 + m_w + mi * 16 + g;
        #pragma unroll
        for (int ni = 0; ni < 4; ni++) {
            int cc = bx * 128 + n_w + ni * 8 + tg * 2;
            float b0 = 0.f, b1 = 0.f;
            if (bias) { b0 = bias[cc]; b1 = bias[cc + 1]; }
            float2 v0 = make_float2(c[mi][ni][0] + b0, c[mi][ni][1] + b1);
            float2 v1 = make_float2(c[mi][ni][2] + b0, c[mi][ni][3] + b1);
            *(float2*)(C + (size_t)r0 * N + cc)       = v0;
            *(float2*)(C + (size_t)(r0 + 8) * N + cc) = v1;
        }
    }
}

// ---------------- row LayerNorm(+bias) + scale/shift + ReLU, in place --------
__global__ __launch_bounds__(128) void ln_bias_relu(
    float* __restrict__ X, const float* __restrict__ bias,
    const float* __restrict__ gamma, const float* __restrict__ beta)
{
    const int row = blockIdx.x;
    const int tid = threadIdx.x;
    float* xp = X + (size_t)row * DD + tid * 4;
    float4 v = *(float4*)xp;
    float4 bb = *(const float4*)(bias + tid * 4);
    v.x += bb.x; v.y += bb.y; v.z += bb.z; v.w += bb.w;

    float s  = v.x + v.y + v.z + v.w;
    float sq = v.x*v.x + v.y*v.y + v.z*v.z + v.w*v.w;
    #pragma unroll
    for (int o = 16; o > 0; o >>= 1) {
        s  += __shfl_down_sync(0xffffffffu, s,  o);
        sq += __shfl_down_sync(0xffffffffu, sq, o);
    }
    __shared__ float ws[4], wq[4];
    if ((tid & 31) == 0) { ws[tid >> 5] = s; wq[tid >> 5] = sq; }
    __syncthreads();
    float st = ws[0] + ws[1] + ws[2] + ws[3];
    float qt = wq[0] + wq[1] + wq[2] + wq[3];
    float mean = st * (1.f / DD);
    float var  = qt * (1.f / DD) - mean * mean;
    float inv  = rsqrtf(var + 1e-6f);

    float4 g = *(const float4*)(gamma + tid * 4);
    float4 b2 = *(const float4*)(beta + tid * 4);
    float4 o;
    o.x = fmaxf((v.x - mean) * inv * g.x + b2.x, 0.f);
    o.y = fmaxf((v.y - mean) * inv * g.y + b2.y, 0.f);
    o.z = fmaxf((v.z - mean) * inv * g.z + b2.z, 0.f);
    o.w = fmaxf((v.w - mean) * inv * g.w + b2.w, 0.f);
    *(float4*)xp = o;
}

// ---------------- persistent GRU scan (tf32 mma + grid barrier) --------------
#define GRU_NBLK 64
#define GRU_SMEM_WORDS (3*512*16 + 128*132)    // Ws + hs = 41472 words

__device__ __forceinline__ float sigmoidf_(float x) { return 1.f / (1.f + expf(-x)); }

__global__ __launch_bounds__(256, 1) void gru_scan(
    const float* __restrict__ hidden,
    const float* __restrict__ X,
    const int* __restrict__ dones,
    const float* __restrict__ Wh,
    const float* __restrict__ bhn,
    float* __restrict__ y)
{
    extern __shared__ uint32_t smem_u[];
    uint32_t* Ws = smem_u;
    uint32_t* hs = smem_u + 3*512*16;

    const int bi = blockIdx.x;
    const int nb = bi >> 5;
    const int nd = bi & 31;
    const int b0 = nb * 128;
    const int d0 = nd * 16;

    const int tid  = threadIdx.x;
    const int warp = tid >> 5, lane = tid & 31;
    const int wm = warp & 3, wn = warp >> 2;
    const int m_base = wm * 32;
    const int n8 = wn * 8;
    const int g  = lane >> 2;
    const int tg = lane & 3;

    #pragma unroll 4
    for (int i = 0; i < 24; i++) {
        int q = tid + i * 256;
        int gate = q >> 11;
        int rem  = q & 2047;
        int k    = rem >> 2;
        int dl4  = (rem & 3) * 4;
        float4 w = *(const float4*)(Wh + ((size_t)gate * 512 + k) * 512 + d0 + dl4);
        uint4 u = make_uint4(f2tf32(w.x), f2tf32(w.y), f2tf32(w.z), f2tf32(w.w));
        *(uint4*)(&Ws[((gate << 9) + k) * 16 + dl4]) = u;
    }

    const int dcol = d0 + n8 + tg * 2;
    const float bh0 = bhn[dcol], bh1 = bhn[dcol + 1];
    __syncthreads();

    for (int t = 0; t < TT; t++) {
        const float* hprev = (t == 0) ? hidden : (y + (size_t)(t - 1) * BD);
        const int* dn = dones + (size_t)t * BB_;

        float2 xr2[4], xz2[4], xn2[4], hp2[4];
        #pragma unroll
        for (int j = 0; j < 4; j++) {
            int bglob = b0 + m_base + j * 8 + g;
            int df = dn[bglob];
            size_t gi = (size_t)bglob * DD + dcol;
            hp2[j] = df ? make_float2(0.f, 0.f) : *(const float2*)(hprev + gi);
            size_t xi = (size_t)t * BD + gi;
            xr2[j] = *(const float2*)(X + xi);
            xz2[j] = *(const float2*)(X + TBD + xi);
            xn2[j] = *(const float2*)(X + 2 * TBD + xi);
        }

        float c[2][3][4];
        #pragma unroll
        for (int mi = 0; mi < 2; mi++)
            #pragma unroll
            for (int gt = 0; gt < 3; gt++)
                #pragma unroll
                for (int q = 0; q < 4; q++) c[mi][gt][q] = 0.f;

        for (int kc = 0; kc < 4; kc++) {
            const int kbase = kc * 128;
            #pragma unroll 4
            for (int i = 0; i < 16; i++) {
                int linear = tid + i * 256;
                int row = linear >> 5;
                int c4  = (linear & 31) * 4;
                int gb  = b0 + row;
                float4 v;
                if (dn[gb]) v = make_float4(0.f, 0.f, 0.f, 0.f);
                else v = *(const float4*)(hprev + (size_t)gb * DD + kbase + c4);
                uint4 u = make_uint4(f2tf32(v.x), f2tf32(v.y), f2tf32(v.z), f2tf32(v.w));
                *(uint4*)(&hs[row * 132 + c4]) = u;
            }
            __syncthreads();

            #pragma unroll 4
            for (int kt = 0; kt < 16; kt++) {
                const int kb = kt * 8;
                uint32_t af[2][4];
                #pragma unroll
                for (int mi = 0; mi < 2; mi++) {
                    int rb = (m_base + mi * 16 + g) * 132;
                    af[mi][0] = hs[rb +       kb + tg    ];
                    af[mi][1] = hs[rb + 8*132 + kb + tg  ];
                    af[mi][2] = hs[rb +       kb + tg + 4];
                    af[mi][3] = hs[rb + 8*132 + kb + tg + 4];
                }
                #pragma unroll
                for (int gt = 0; gt < 3; gt++) {
                    int kg = kbase + kb;
                    uint32_t b0r = Ws[((gt << 9) + kg + tg    ) * 16 + n8 + g];
                    uint32_t b1r = Ws[((gt << 9) + kg + tg + 4) * 16 + n8 + g];
                    #pragma unroll
                    for (int mi = 0; mi < 2; mi++) {
                        asm volatile(
                            "mma.sync.aligned.m16n8k8.row.col.f32.tf32.tf32.f32 "
                            "{%0,%1,%2,%3}, {%4,%5,%6,%7}, {%8,%9}, {%0,%1,%2,%3};"
                            : "+f"(c[mi][gt][0]), "+f"(c[mi][gt][1]),
                              "+f"(c[mi][gt][2]), "+f"(c[mi][gt][3])
                            : "r"(af[mi][0]), "r"(af[mi][1]), "r"(af[mi][2]), "r"(af[mi][3]),
                              "r"(b0r), "r"(b1r));
                    }
                }
            }
            __syncthreads();
        }

        #pragma unroll
        for (int mi = 0; mi < 2; mi++) {
            #pragma unroll
            for (int half = 0; half < 2; half++) {
                int j = mi * 2 + half;
                int q0 = half * 2;
                int bglob = b0 + m_base + j * 8 + g;
                float r0 = sigmoidf_(xr2[j].x + c[mi][0][q0]);
                float r1 = sigmoidf_(xr2[j].y + c[mi][0][q0 + 1]);
                float z0 = sigmoidf_(xz2[j].x + c[mi][1][q0]);
                float z1 = sigmoidf_(xz2[j].y + c[mi][1][q0 + 1]);
                float n0 = tanhf(xn2[j].x + r0 * (c[mi][2][q0]     + bh0));
                float n1 = tanhf(xn2[j].y + r1 * (c[mi][2][q0 + 1] + bh1));
                float2 o;
                o.x = (1.f - z0) * n0 + z0 * hp2[j].x;
                o.y = (1.f - z1) * n1 + z1 * hp2[j].y;
                *(float2*)(y + (size_t)t * BD + (size_t)bglob * DD + dcol) = o;
            }
        }

        grid_barrier(GRU_NBLK);
    }
}

// ---------------- actor head: logits = X@Wa + ba, availability mask ----------
__global__ __launch_bounds__(256) void head_gemm(
    const float* __restrict__ X, const float* __restrict__ Wa,
    const float* __restrict__ ba, const int* __restrict__ avail,
    float* __restrict__ out, int M)
{
    const int r = blockIdx.x * 8 + (threadIdx.x >> 5);
    const int a = threadIdx.x & 31;
    const float* xr = X + (size_t)r * DD;
    float acc = 0.f;
    #pragma unroll 8
    for (int k = 0; k < DD; k += 4) {
        float4 xv = *(const float4*)(xr + k);
        acc += xv.x * __ldg(Wa + (k + 0) * AA + a);
        acc += xv.y * __ldg(Wa + (k + 1) * AA + a);
        acc += xv.z * __ldg(Wa + (k + 2) * AA + a);
        acc += xv.w * __ldg(Wa + (k + 3) * AA + a);
    }
    float av = (float)avail[(size_t)r * AA + a];
    out[(size_t)r * AA + a] = acc + ba[a] - (1.f - av) * 1e10f;
}

__global__ void copy_kernel(const float* __restrict__ src, float* __restrict__ dst, int n)
{
    int i = blockIdx.x * blockDim.x + threadIdx.x;
    if (i < n) dst[i] = src[i];
}

// ---------------- host orchestration ----------------------------------------
extern "C" void kernel_launch(void* const* d_in, const int* in_sizes, int n_in,
                              void* d_out, int out_size)
{
    const float*          hidden = (const float*)d_in[0];
    const float*          obs    = (const float*)d_in[1];
    const int*            dones  = (const int*)d_in[2];   // bool promoted to int32
    const int*            avail  = (const int*)d_in[3];
    const float*          Wm     = (const float*)d_in[4];
    const float*          bm     = (const float*)d_in[5];
    const float*          lns    = (const float*)d_in[6];
    const float*          lnb    = (const float*)d_in[7];
    const float*          Wi     = (const float*)d_in[8];
    const float*          bi     = (const float*)d_in[9];
    const float*          Wh     = (const float*)d_in[10];
    const float*          bhn    = (const float*)d_in[11];
    const float*          Wo     = (const float*)d_in[12];
    const float*          bo     = (const float*)d_in[13];
    const float*          ln2s   = (const float*)d_in[14];
    const float*          ln2b   = (const float*)d_in[15];
    const float*          Wa     = (const float*)d_in[16];
    const float*          ba     = (const float*)d_in[17];
    float* out = (float*)d_out;

    float *bufA, *bufB, *Xbuf, *ybuf;
    cudaGetSymbolAddress((void**)&bufA, g_bufA);
    cudaGetSymbolAddress((void**)&bufB, g_bufB);
    cudaGetSymbolAddress((void**)&Xbuf, g_X);
    cudaGetSymbolAddress((void**)&ybuf, g_y);

    cudaFuncSetAttribute(gemm_tf32, cudaFuncAttributeMaxDynamicSharedMemorySize, GEMM_SMEM_BYTES);

    const dim3 ggrid(DD / 128, MM / 128);   // (4, 512)
    float* bufs[2] = {bufA, bufB};

    // --- MLP encoder: 3x (GEMM -> LN(+bias) -> ReLU), ping-pong buffers ---
    const float* cur = obs;
    for (int l = 0; l < LL; l++) {
        float* dst = bufs[l & 1];
        gemm_tf32<<<ggrid, 256, GEMM_SMEM_BYTES>>>(cur, Wm + (size_t)l * DD * DD, dst, nullptr, MM, DD, DD);
        ln_bias_relu<<<MM, 128>>>(dst, bm + l * DD, lns + l * DD, lnb + l * DD);
        cur = dst;
    }

    // --- precompute input-gate activations for all t: X[g] = e @ Wi[g] + bi[g]
    for (int g = 0; g < 3; g++) {
        gemm_tf32<<<ggrid, 256, GEMM_SMEM_BYTES>>>(cur, Wi + (size_t)g * DD * DD,
                                                   Xbuf + (size_t)g * TBD, bi + g * DD, MM, DD, DD);
    }

    // --- persistent GRU scan: all 256 steps in one kernel ---
    static const int gru_smem = GRU_SMEM_WORDS * 4;   // 165888 bytes
    cudaFuncSetAttribute(gru_scan, cudaFuncAttributeMaxDynamicSharedMemorySize, gru_smem);
    gru_scan<<<GRU_NBLK, 256, gru_smem>>>(hidden, Xbuf, dones, Wh, bhn, ybuf);

    // --- actor head ---
    gemm_tf32<<<ggrid, 256, GEMM_SMEM_BYTES>>>(ybuf, Wo, bufB, nullptr, MM, DD, DD);
    ln_bias_relu<<<MM, 128>>>(bufB, bo, ln2s, ln2b);

    bool has_hidden = (out_size >= (int)(BD + (size_t)MM * AA));
    float* logits_out = out + (has_hidden ? BD : 0);
    head_gemm<<<MM / 8, 256>>>(bufB, Wa, ba, avail, logits_out, MM);

    if (has_hidden) {
        copy_kernel<<<(BD + 255) / 256, 256>>>(ybuf + (size_t)(TT - 1) * BD, out, BD);
    }
}

// round 12
// speedup vs baseline: 1.8768x; 1.0092x over previous
#include <cuda_runtime.h>
#include <cuda_bf16.h>
#include <math.h>
#include <stdint.h>

#define TT 256
#define BB_ 256
#define DD 512
#define AA 32
#define LL 3
#define MM (TT*BB_)            // 65536 rows
#define TBD ((size_t)MM*DD)    // 33554432
#define BD (BB_*DD)            // 131072

// ---------------- scratch (device globals; no runtime allocation) -----------
__device__ float g_bufA[TT*BB_*DD];
__device__ float g_bufB[TT*BB_*DD];
__device__ float g_X[3ull*TT*BB_*DD];
__device__ float g_y[TT*BB_*DD];

// grid-barrier state for persistent GRU scan
__device__ unsigned g_bar_count = 0;
__device__ unsigned g_bar_gen   = 0;

// ---------------- helpers ----------------------------------------------------
__device__ __forceinline__ uint32_t f2tf32(float x) {
    uint32_t r;
    asm("cvt.rna.tf32.f32 %0, %1;" : "=r"(r) : "f"(x));
    return r;
}

__device__ __forceinline__ void cp_async16(void* smem_ptr, const void* gmem_ptr) {
    uint32_t s = (uint32_t)__cvta_generic_to_shared(smem_ptr);
    asm volatile("cp.async.cg.shared.global [%0], [%1], 16;" :: "r"(s), "l"(gmem_ptr));
}

__device__ __forceinline__ unsigned ld_acquire_u32(unsigned* p) {
    unsigned v;
    asm volatile("ld.acquire.gpu.u32 %0, [%1];" : "=r"(v) : "l"(p) : "memory");
    return v;
}

// release/acquire grid barrier; all NBLK blocks must be co-resident
__device__ __forceinline__ void grid_barrier(unsigned nblk) {
    __threadfence();
    __syncthreads();
    if (threadIdx.x == 0) {
        unsigned gen = *((volatile unsigned*)&g_bar_gen);   // read BEFORE arrive
        unsigned arrived = atomicAdd(&g_bar_count, 1u);
        if (arrived == nblk - 1) {
            g_bar_count = 0;
            __threadfence();
            atomicAdd(&g_bar_gen, 1u);
        } else {
            while (ld_acquire_u32(&g_bar_gen) == gen) { __nanosleep(64); }
        }
    }
    __syncthreads();
}

// ---------------- TF32 tensor-core GEMM 128x128x32, cp.async 3-stage ---------
// C[M,N] = A[M,K] @ W[K,N] (+ bias[N]); M%128==0, N%128==0, K%32==0
// dynamic smem: As[3][128][36] + Bs[3][32][136] raw fp32 (105 KB)
#define AS_STRIDE 4608
#define BS_STRIDE 4352
#define GEMM_SMEM_BYTES ((3*AS_STRIDE + 3*BS_STRIDE) * 4)

__global__ __launch_bounds__(256, 2) void gemm_tf32(
    const float* __restrict__ A, const float* __restrict__ W,
    float* __restrict__ C, const float* __restrict__ bias,
    int M, int N, int K)
{
    extern __shared__ float sm[];
    float* AsBase = sm;                       // stage s at s*4608, [row*36 + k]
    float* BsBase = sm + 3 * AS_STRIDE;       // stage s at s*4352, [krow*136 + n]

    const int bx = blockIdx.x;
    const int by = blockIdx.y;
    const int tid = threadIdx.x;
    const int warp = tid >> 5, lane = tid & 31;
    const int wm = warp & 1, wn = warp >> 1;
    const int m_w = wm * 64, n_w = wn * 32;
    const int g  = lane >> 2;
    const int tg = lane & 3;

    const float* Ab = A + (size_t)by * 128 * K;
    const float* Wb = W + (size_t)bx * 128;

    // per-thread load coords
    const int a_row = tid >> 1;                 // 0..127  (2 threads/row)
    const int a_kq  = (tid & 1) * 16;           // float index 0 or 16; FOUR 16B each
    const int b_kr  = tid >> 5;                 // 0..7
    const int b_nq  = (tid & 31) * 4;

    float c[4][4][4];
    #pragma unroll
    for (int i = 0; i < 4; i++)
        #pragma unroll
        for (int j = 0; j < 4; j++)
            #pragma unroll
            for (int q = 0; q < 4; q++) c[i][j][q] = 0.f;

    // async load of one 128x32 A tile + 32x128 B tile into stage s
    auto issue_load = [&](int k0, int s) {
        float* As = AsBase + s * AS_STRIDE;
        float* Bs = BsBase + s * BS_STRIDE;
        #pragma unroll
        for (int i = 0; i < 4; i++) {
            cp_async16(&As[a_row * 36 + a_kq + i * 4],
                       Ab + (size_t)a_row * K + k0 + a_kq + i * 4);
        }
        #pragma unroll
        for (int i = 0; i < 4; i++) {
            int kr = b_kr + i * 8;
            cp_async16(&Bs[kr * 136 + b_nq],
                       Wb + (size_t)(k0 + kr) * N + b_nq);
        }
        asm volatile("cp.async.commit_group;");
    };

    // prologue: two stages in flight
    issue_load(0, 0);
    if (K > 32) issue_load(32, 1);

    int s = 0;
    for (int k0 = 0; k0 < K; k0 += 32) {
        // issue stage s+2, then wait for oldest (stage s)
        if (k0 + 64 < K) {
            int s2 = s + 2; if (s2 >= 3) s2 -= 3;
            issue_load(k0 + 64, s2);
            asm volatile("cp.async.wait_group 2;");
        } else if (k0 + 32 < K) {
            asm volatile("cp.async.wait_group 1;");
        } else {
            asm volatile("cp.async.wait_group 0;");
        }
        __syncthreads();

        const float* As = AsBase + s * AS_STRIDE;
        const float* Bs = BsBase + s * BS_STRIDE;

        // fragment loaders for one kk (8 k-values)
        uint32_t afX[4][4], bfX[4][2];   // buffer X
        uint32_t afY[4][4], bfY[4][2];   // buffer Y
        auto load_frags = [&](int kk, uint32_t af[4][4], uint32_t bf[4][2]) {
            const int kb = kk * 8;
            #pragma unroll
            for (int mi = 0; mi < 4; mi++) {
                int rb = m_w + mi * 16;
                af[mi][0] = f2tf32(As[(rb + g    ) * 36 + kb + tg    ]);
                af[mi][1] = f2tf32(As[(rb + g + 8) * 36 + kb + tg    ]);
                af[mi][2] = f2tf32(As[(rb + g    ) * 36 + kb + tg + 4]);
                af[mi][3] = f2tf32(As[(rb + g + 8) * 36 + kb + tg + 4]);
            }
            #pragma unroll
            for (int ni = 0; ni < 4; ni++) {
                int nb = n_w + ni * 8;
                bf[ni][0] = f2tf32(Bs[(kb + tg    ) * 136 + nb + g]);
                bf[ni][1] = f2tf32(Bs[(kb + tg + 4) * 136 + nb + g]);
            }
        };
        auto do_mma = [&](uint32_t af[4][4], uint32_t bf[4][2]) {
            #pragma unroll
            for (int mi = 0; mi < 4; mi++)
                #pragma unroll
                for (int ni = 0; ni < 4; ni++) {
                    asm volatile(
                        "mma.sync.aligned.m16n8k8.row.col.f32.tf32.tf32.f32 "
                        "{%0,%1,%2,%3}, {%4,%5,%6,%7}, {%8,%9}, {%0,%1,%2,%3};"
                        : "+f"(c[mi][ni][0]), "+f"(c[mi][ni][1]),
                          "+f"(c[mi][ni][2]), "+f"(c[mi][ni][3])
                        : "r"(af[mi][0]), "r"(af[mi][1]), "r"(af[mi][2]), "r"(af[mi][3]),
                          "r"(bf[ni][0]), "r"(bf[ni][1]));
                }
        };

        // kk pipeline: load next fragments while mma'ing current
        load_frags(0, afX, bfX);
        load_frags(1, afY, bfY);
        do_mma(afX, bfX);
        load_frags(2, afX, bfX);
        do_mma(afY, bfY);
        load_frags(3, afY, bfY);
        do_mma(afX, bfX);
        do_mma(afY, bfY);

        __syncthreads();   // protect stage s before it is re-issued (s+3 ≡ s)
        s = s + 1; if (s >= 3) s -= 3;
    }

    #pragma unroll
    for (int mi = 0; mi < 4; mi++) {
        int r0 = by * 128 + m_w + mi * 16 + g;
        #pragma unroll
        for (int ni = 0; ni < 4; ni++) {
            int cc = bx * 128 + n_w + ni * 8 + tg * 2;
            float b0 = 0.f, b1 = 0.f;
            if (bias) { b0 = bias[cc]; b1 = bias[cc + 1]; }
            float2 v0 = make_float2(c[mi][ni][0] + b0, c[mi][ni][1] + b1);
            float2 v1 = make_float2(c[mi][ni][2] + b0, c[mi][ni][3] + b1);
            *(float2*)(C + (size_t)r0 * N + cc)       = v0;
            *(float2*)(C + (size_t)(r0 + 8) * N + cc) = v1;
        }
    }
}

// ---------------- row LayerNorm(+bias) + scale/shift + ReLU, in place --------
__global__ __launch_bounds__(128) void ln_bias_relu(
    float* __restrict__ X, const float* __restrict__ bias,
    const float* __restrict__ gamma, const float* __restrict__ beta)
{
    const int row = blockIdx.x;
    const int tid = threadIdx.x;
    float* xp = X + (size_t)row * DD + tid * 4;
    float4 v = *(float4*)xp;
    float4 bb = *(const float4*)(bias + tid * 4);
    v.x += bb.x; v.y += bb.y; v.z += bb.z; v.w += bb.w;

    float s  = v.x + v.y + v.z + v.w;
    float sq = v.x*v.x + v.y*v.y + v.z*v.z + v.w*v.w;
    #pragma unroll
    for (int o = 16; o > 0; o >>= 1) {
        s  += __shfl_down_sync(0xffffffffu, s,  o);
        sq += __shfl_down_sync(0xffffffffu, sq, o);
    }
    __shared__ float ws[4], wq[4];
    if ((tid & 31) == 0) { ws[tid >> 5] = s; wq[tid >> 5] = sq; }
    __syncthreads();
    float st = ws[0] + ws[1] + ws[2] + ws[3];
    float qt = wq[0] + wq[1] + wq[2] + wq[3];
    float mean = st * (1.f / DD);
    float var  = qt * (1.f / DD) - mean * mean;
    float inv  = rsqrtf(var + 1e-6f);

    float4 g = *(const float4*)(gamma + tid * 4);
    float4 b2 = *(const float4*)(beta + tid * 4);
    float4 o;
    o.x = fmaxf((v.x - mean) * inv * g.x + b2.x, 0.f);
    o.y = fmaxf((v.y - mean) * inv * g.y + b2.y, 0.f);
    o.z = fmaxf((v.z - mean) * inv * g.z + b2.z, 0.f);
    o.w = fmaxf((v.w - mean) * inv * g.w + b2.w, 0.f);
    *(float4*)xp = o;
}

// ---------------- persistent GRU scan (tf32 mma + grid barrier) --------------
#define GRU_NBLK 64
#define GRU_SMEM_WORDS (3*512*16 + 128*132)    // Ws + hs = 41472 words

__device__ __forceinline__ float sigmoidf_(float x) { return 1.f / (1.f + expf(-x)); }

__global__ __launch_bounds__(256, 1) void gru_scan(
    const float* __restrict__ hidden,
    const float* __restrict__ X,
    const int* __restrict__ dones,
    const float* __restrict__ Wh,
    const float* __restrict__ bhn,
    float* __restrict__ y)
{
    extern __shared__ uint32_t smem_u[];
    uint32_t* Ws = smem_u;
    uint32_t* hs = smem_u + 3*512*16;

    const int bi = blockIdx.x;
    const int nb = bi >> 5;
    const int nd = bi & 31;
    const int b0 = nb * 128;
    const int d0 = nd * 16;

    const int tid  = threadIdx.x;
    const int warp = tid >> 5, lane = tid & 31;
    const int wm = warp & 3, wn = warp >> 2;
    const int m_base = wm * 32;
    const int n8 = wn * 8;
    const int g  = lane >> 2;
    const int tg = lane & 3;

    #pragma unroll 4
    for (int i = 0; i < 24; i++) {
        int q = tid + i * 256;
        int gate = q >> 11;
        int rem  = q & 2047;
        int k    = rem >> 2;
        int dl4  = (rem & 3) * 4;
        float4 w = *(const float4*)(Wh + ((size_t)gate * 512 + k) * 512 + d0 + dl4);
        uint4 u = make_uint4(f2tf32(w.x), f2tf32(w.y), f2tf32(w.z), f2tf32(w.w));
        *(uint4*)(&Ws[((gate << 9) + k) * 16 + dl4]) = u;
    }

    const int dcol = d0 + n8 + tg * 2;
    const float bh0 = bhn[dcol], bh1 = bhn[dcol + 1];
    __syncthreads();

    for (int t = 0; t < TT; t++) {
        const float* hprev = (t == 0) ? hidden : (y + (size_t)(t - 1) * BD);
        const int* dn = dones + (size_t)t * BB_;

        float2 xr2[4], xz2[4], xn2[4], hp2[4];
        #pragma unroll
        for (int j = 0; j < 4; j++) {
            int bglob = b0 + m_base + j * 8 + g;
            int df = dn[bglob];
            size_t gi = (size_t)bglob * DD + dcol;
            hp2[j] = df ? make_float2(0.f, 0.f) : *(const float2*)(hprev + gi);
            size_t xi = (size_t)t * BD + gi;
            xr2[j] = *(const float2*)(X + xi);
            xz2[j] = *(const float2*)(X + TBD + xi);
            xn2[j] = *(const float2*)(X + 2 * TBD + xi);
        }

        float c[2][3][4];
        #pragma unroll
        for (int mi = 0; mi < 2; mi++)
            #pragma unroll
            for (int gt = 0; gt < 3; gt++)
                #pragma unroll
                for (int q = 0; q < 4; q++) c[mi][gt][q] = 0.f;

        for (int kc = 0; kc < 4; kc++) {
            const int kbase = kc * 128;
            #pragma unroll 4
            for (int i = 0; i < 16; i++) {
                int linear = tid + i * 256;
                int row = linear >> 5;
                int c4  = (linear & 31) * 4;
                int gb  = b0 + row;
                float4 v;
                if (dn[gb]) v = make_float4(0.f, 0.f, 0.f, 0.f);
                else v = *(const float4*)(hprev + (size_t)gb * DD + kbase + c4);
                uint4 u = make_uint4(f2tf32(v.x), f2tf32(v.y), f2tf32(v.z), f2tf32(v.w));
                *(uint4*)(&hs[row * 132 + c4]) = u;
            }
            __syncthreads();

            #pragma unroll 4
            for (int kt = 0; kt < 16; kt++) {
                const int kb = kt * 8;
                uint32_t af[2][4];
                #pragma unroll
                for (int mi = 0; mi < 2; mi++) {
                    int rb = (m_base + mi * 16 + g) * 132;
                    af[mi][0] = hs[rb +       kb + tg    ];
                    af[mi][1] = hs[rb + 8*132 + kb + tg  ];
                    af[mi][2] = hs[rb +       kb + tg + 4];
                    af[mi][3] = hs[rb + 8*132 + kb + tg + 4];
                }
                #pragma unroll
                for (int gt = 0; gt < 3; gt++) {
                    int kg = kbase + kb;
                    uint32_t b0r = Ws[((gt << 9) + kg + tg    ) * 16 + n8 + g];
                    uint32_t b1r = Ws[((gt << 9) + kg + tg + 4) * 16 + n8 + g];
                    #pragma unroll
                    for (int mi = 0; mi < 2; mi++) {
                        asm volatile(
                            "mma.sync.aligned.m16n8k8.row.col.f32.tf32.tf32.f32 "
                            "{%0,%1,%2,%3}, {%4,%5,%6,%7}, {%8,%9}, {%0,%1,%2,%3};"
                            : "+f"(c[mi][gt][0]), "+f"(c[mi][gt][1]),
                              "+f"(c[mi][gt][2]), "+f"(c[mi][gt][3])
                            : "r"(af[mi][0]), "r"(af[mi][1]), "r"(af[mi][2]), "r"(af[mi][3]),
                              "r"(b0r), "r"(b1r));
                    }
                }
            }
            __syncthreads();
        }

        #pragma unroll
        for (int mi = 0; mi < 2; mi++) {
            #pragma unroll
            for (int half = 0; half < 2; half++) {
                int j = mi * 2 + half;
                int q0 = half * 2;
                int bglob = b0 + m_base + j * 8 + g;
                float r0 = sigmoidf_(xr2[j].x + c[mi][0][q0]);
                float r1 = sigmoidf_(xr2[j].y + c[mi][0][q0 + 1]);
                float z0 = sigmoidf_(xz2[j].x + c[mi][1][q0]);
                float z1 = sigmoidf_(xz2[j].y + c[mi][1][q0 + 1]);
                float n0 = tanhf(xn2[j].x + r0 * (c[mi][2][q0]     + bh0));
                float n1 = tanhf(xn2[j].y + r1 * (c[mi][2][q0 + 1] + bh1));
                float2 o;
                o.x = (1.f - z0) * n0 + z0 * hp2[j].x;
                o.y = (1.f - z1) * n1 + z1 * hp2[j].y;
                *(float2*)(y + (size_t)t * BD + (size_t)bglob * DD + dcol) = o;
            }
        }

        grid_barrier(GRU_NBLK);
    }
}

// ---------------- actor head: logits = X@Wa + ba, availability mask ----------
__global__ __launch_bounds__(256) void head_gemm(
    const float* __restrict__ X, const float* __restrict__ Wa,
    const float* __restrict__ ba, const int* __restrict__ avail,
    float* __restrict__ out, int M)
{
    const int r = blockIdx.x * 8 + (threadIdx.x >> 5);
    const int a = threadIdx.x & 31;
    const float* xr = X + (size_t)r * DD;
    float acc = 0.f;
    #pragma unroll 8
    for (int k = 0; k < DD; k += 4) {
        float4 xv = *(const float4*)(xr + k);
        acc += xv.x * __ldg(Wa + (k + 0) * AA + a);
        acc += xv.y * __ldg(Wa + (k + 1) * AA + a);
        acc += xv.z * __ldg(Wa + (k + 2) * AA + a);
        acc += xv.w * __ldg(Wa + (k + 3) * AA + a);
    }
    float av = (float)avail[(size_t)r * AA + a];
    out[(size_t)r * AA + a] = acc + ba[a] - (1.f - av) * 1e10f;
}

__global__ void copy_kernel(const float* __restrict__ src, float* __restrict__ dst, int n)
{
    int i = blockIdx.x * blockDim.x + threadIdx.x;
    if (i < n) dst[i] = src[i];
}

// ---------------- host orchestration ----------------------------------------
extern "C" void kernel_launch(void* const* d_in, const int* in_sizes, int n_in,
                              void* d_out, int out_size)
{
    const float*          hidden = (const float*)d_in[0];
    const float*          obs    = (const float*)d_in[1];
    const int*            dones  = (const int*)d_in[2];   // bool promoted to int32
    const int*            avail  = (const int*)d_in[3];
    const float*          Wm     = (const float*)d_in[4];
    const float*          bm     = (const float*)d_in[5];
    const float*          lns    = (const float*)d_in[6];
    const float*          lnb    = (const float*)d_in[7];
    const float*          Wi     = (const float*)d_in[8];
    const float*          bi     = (const float*)d_in[9];
    const float*          Wh     = (const float*)d_in[10];
    const float*          bhn    = (const float*)d_in[11];
    const float*          Wo     = (const float*)d_in[12];
    const float*          bo     = (const float*)d_in[13];
    const float*          ln2s   = (const float*)d_in[14];
    const float*          ln2b   = (const float*)d_in[15];
    const float*          Wa     = (const float*)d_in[16];
    const float*          ba     = (const float*)d_in[17];
    float* out = (float*)d_out;

    float *bufA, *bufB, *Xbuf, *ybuf;
    cudaGetSymbolAddress((void**)&bufA, g_bufA);
    cudaGetSymbolAddress((void**)&bufB, g_bufB);
    cudaGetSymbolAddress((void**)&Xbuf, g_X);
    cudaGetSymbolAddress((void**)&ybuf, g_y);

    cudaFuncSetAttribute(gemm_tf32, cudaFuncAttributeMaxDynamicSharedMemorySize, GEMM_SMEM_BYTES);

    const dim3 ggrid(DD / 128, MM / 128);   // (4, 512)
    float* bufs[2] = {bufA, bufB};

    // --- MLP encoder: 3x (GEMM -> LN(+bias) -> ReLU), ping-pong buffers ---
    const float* cur = obs;
    for (int l = 0; l < LL; l++) {
        float* dst = bufs[l & 1];
        gemm_tf32<<<ggrid, 256, GEMM_SMEM_BYTES>>>(cur, Wm + (size_t)l * DD * DD, dst, nullptr, MM, DD, DD);
        ln_bias_relu<<<MM, 128>>>(dst, bm + l * DD, lns + l * DD, lnb + l * DD);
        cur = dst;
    }

    // --- precompute input-gate activations for all t: X[g] = e @ Wi[g] + bi[g]
    for (int g = 0; g < 3; g++) {
        gemm_tf32<<<ggrid, 256, GEMM_SMEM_BYTES>>>(cur, Wi + (size_t)g * DD * DD,
                                                   Xbuf + (size_t)g * TBD, bi + g * DD, MM, DD, DD);
    }

    // --- persistent GRU scan: all 256 steps in one kernel ---
    static const int gru_smem = GRU_SMEM_WORDS * 4;   // 165888 bytes
    cudaFuncSetAttribute(gru_scan, cudaFuncAttributeMaxDynamicSharedMemorySize, gru_smem);
    gru_scan<<<GRU_NBLK, 256, gru_smem>>>(hidden, Xbuf, dones, Wh, bhn, ybuf);

    // --- actor head ---
    gemm_tf32<<<ggrid, 256, GEMM_SMEM_BYTES>>>(ybuf, Wo, bufB, nullptr, MM, DD, DD);
    ln_bias_relu<<<MM, 128>>>(bufB, bo, ln2s, ln2b);

    bool has_hidden = (out_size >= (int)(BD + (size_t)MM * AA));
    float* logits_out = out + (has_hidden ? BD : 0);
    head_gemm<<<MM / 8, 256>>>(bufB, Wa, ba, avail, logits_out, MM);

    if (has_hidden) {
        copy_kernel<<<(BD + 255) / 256, 256>>>(ybuf + (size_t)(TT - 1) * BD, out, BD);
    }
}